// round 13
// baseline (speedup 1.0000x reference)
#include <cuda_runtime.h>
#include <math_constants.h>

#define NPTS   8192
#define BATCH  4
#define KNN    4
#define QPB    224
#define THREADS 896                // 28 warps; warp-cooperative, 8 queries/warp
#define GRPX   37                  // 37*4 = 148 blocks = 1 full wave
#define QPW    8

#define NBINS  512
#define XMIN   (-6.0f)
#define BINW   (12.0f / NBINS)
#define INVW   (NBINS / 12.0f)
#define SLACK  1e-3f               // >> all fp32 rounding at these magnitudes
#define GUARD  64                  // sentinels each side; covers 64-wide chunk overshoot

#define PTS_BYTES ((NPTS + 2 * GUARD) * 16)
#define IDX_BYTES (NPTS * 4)
#define SMEM_BYTES (PTS_BYTES + 2 * IDX_BYTES + NBINS * 4 * 2)   // 203776 B

#define FULL 0xFFFFFFFFu

__device__ __forceinline__ int bin_of(float px) {
    int bin = (int)__fmul_rn(__fsub_rn(px, XMIN), INVW);
    return min(max(bin, 0), NBINS - 1);
}

__device__ __forceinline__ bool better(float s, int oj, float v, int iv) {
    return (s > v) | ((s == v) & (oj < iv));
}

// Insert (cs, coj, cps) into the replicated top-4; updates d4sq/xlim on change.
#define INSERT_CAND(cs, coj, cps)                                              \
    do {                                                                       \
        if (better(cs, coj, v3, o3)) {                                         \
            if (better(cs, coj, v2, o2)) {                                     \
                v3 = v2; o3 = o2; p3 = p2;                                     \
                if (better(cs, coj, v1, o1)) {                                 \
                    v2 = v1; o2 = o1; p2 = p1;                                 \
                    if (better(cs, coj, v0, o0)) {                             \
                        v1 = v0; o1 = o0; p1 = p0;                             \
                        v0 = cs; o0 = coj; p0 = cps;                           \
                    } else { v1 = cs; o1 = coj; p1 = cps; }                    \
                } else { v2 = cs; o2 = coj; p2 = cps; }                        \
            } else { v3 = cs; o3 = coj; p3 = cps; }                            \
            d4sq = qh2 - 2.0f * v3 + SLACK;                                    \
            xlim = __fadd_ru(BINW, __fsqrt_ru(d4sq));                          \
        }                                                                      \
    } while (0)

__global__ __launch_bounds__(THREADS, 1)
void knn_sorted_kernel(const float* __restrict__ x, float* __restrict__ out) {
    extern __shared__ char smem_raw[];
    float4* __restrict__ pts_s   = (float4*)smem_raw + GUARD;   // logical [-GUARD, NPTS+GUARD)
    int*    __restrict__ idx_s   = (int*)(smem_raw + PTS_BYTES);
    int*    __restrict__ rank_of = (int*)(smem_raw + PTS_BYTES + IDX_BYTES);
    int*    __restrict__ cnt     = (int*)(smem_raw + PTS_BYTES + 2 * IDX_BYTES);
    int*    __restrict__ tmp     = cnt + NBINS;

    const int b = blockIdx.y;
    const float* __restrict__ xb = x + (size_t)b * NPTS * 3;
    const int tid = threadIdx.x;

    // ---- 0) sentinels: beyond==true, s==-inf/NaN -> never a candidate
    if (tid < 2 * GUARD) {
        const int pos = (tid < GUARD) ? (tid - GUARD) : (NPTS + tid - GUARD);
        const float gx = (tid < GUARD) ? -1e30f : 1e30f;
        pts_s[pos] = make_float4(gx, 0.0f, 0.0f, -CUDART_INF_F);
    }

    // ---- 1) histogram over x-bins
    for (int i = tid; i < NBINS; i += THREADS) cnt[i] = 0;
    __syncthreads();
    for (int j = tid; j < NPTS; j += THREADS)
        atomicAdd(&cnt[bin_of(xb[3 * j])], 1);
    __syncthreads();

    // ---- 2) exclusive prefix (Kogge-Stone)
    if (tid < NBINS) tmp[tid] = cnt[tid];
    __syncthreads();
    for (int d = 1; d < NBINS; d <<= 1) {
        int v = 0;
        if (tid < NBINS && tid >= d) v = tmp[tid - d];
        __syncthreads();
        if (tid < NBINS) tmp[tid] += v;
        __syncthreads();
    }
    if (tid < NBINS) cnt[tid] = tmp[tid] - cnt[tid];
    __syncthreads();

    // ---- 3) scatter into bin-sorted order; record each original index's rank
    for (int j = tid; j < NPTS; j += THREADS) {
        float px = xb[3 * j + 0];
        float py = xb[3 * j + 1];
        float pz = xb[3 * j + 2];
        int pos = atomicAdd(&cnt[bin_of(px)], 1);
        pts_s[pos] = make_float4(px, py, pz, -0.5f * (px * px + py * py + pz * pz));
        idx_s[pos] = j;
        rank_of[j] = pos;
    }
    __syncthreads();

    // ---- 4) warp-cooperative queries
    const int w = tid >> 5, l = tid & 31;

    for (int qq = 0; qq < QPW; ++qq) {
        const int q = blockIdx.x * QPB + w * QPW + qq;   // warp-uniform
        if (q >= NPTS) break;

        const int r = rank_of[q];
        const float4 qp = pts_s[r];
        const float qx = qp.x, qy = qp.y, qz = qp.z;
        const float qh2 = -2.0f * qp.w;                  // ||q||^2

        float v0 = -CUDART_INF_F, v1 = -CUDART_INF_F, v2 = -CUDART_INF_F, v3 = -CUDART_INF_F;
        int   o0 = 0, o1 = 0, o2 = 0, o3 = 0;
        int   p0 = 0, p1 = 0, p2 = 0, p3 = 0;
        float d4sq = CUDART_INF_F, xlim = CUDART_INF_F;

        // ---- 4a) seed: 32-rank window [lo, hi] (>=16 cands incl. self)
        const int lo = max(0, r - 16);
        const int hi = min(NPTS - 1, r + 15);
        {
            const int pos = lo + l;
            const bool valid = (pos <= hi);
            float s = -CUDART_INF_F;
            if (valid) {
                const float4 p = pts_s[pos];
                s = __fmaf_rn(qx, p.x, p.w);
                s = __fmaf_rn(qy, p.y, s);
                s = __fmaf_rn(qz, p.z, s);
            }
            unsigned cand = __ballot_sync(FULL, valid);
            while (cand) {
                const int src = __ffs(cand) - 1;
                cand &= cand - 1;
                const float cs  = __shfl_sync(FULL, s, src);
                const int   cps = __shfl_sync(FULL, pos, src);
                const int   coj = idx_s[cps];
                INSERT_CAND(cs, coj, cps);
            }
        }

        // ---- 4b) chunked walk, 64 candidates/iteration (2 per lane)
        #pragma unroll
        for (int dir = 0; dir < 2; ++dir) {
            int base = dir ? (lo - 1) : (hi + 1);        // first unseen rank

            for (;;) {
                const int posA = dir ? (base - l)  : (base + l);
                const int posB = dir ? (posA - 32) : (posA + 32);
                const float4 pA = pts_s[posA];           // guards make these safe
                const float4 pB = pts_s[posB];
                const float dxA = dir ? (qx - pA.x) : (pA.x - qx);
                const float dxB = dir ? (qx - pB.x) : (pB.x - qx);
                const bool beyA = dxA > xlim;            // sound prune (BINW folded in)
                const bool beyB = dxB > xlim;
                float sA = __fmaf_rn(qx, pA.x, pA.w);
                sA = __fmaf_rn(qy, pA.y, sA);
                sA = __fmaf_rn(qz, pA.z, sA);
                float sB = __fmaf_rn(qx, pB.x, pB.w);
                sB = __fmaf_rn(qy, pB.y, sB);
                sB = __fmaf_rn(qz, pB.z, sB);
                const bool cA = (sA >= v3);              // NaN/-inf-safe: false
                const bool cB = (sB >= v3);

                const unsigned bm = __ballot_sync(FULL, beyA | beyB | cA | cB);
                if (bm) {                                // rare after seeding
                    const unsigned stopm = __ballot_sync(FULL, beyA | beyB);
                    unsigned mA = __ballot_sync(FULL, cA);
                    while (mA) {
                        const int src = __ffs(mA) - 1;
                        mA &= mA - 1;
                        const float cs  = __shfl_sync(FULL, sA, src);
                        const int   cps = __shfl_sync(FULL, posA, src);
                        const int   coj = idx_s[cps];
                        INSERT_CAND(cs, coj, cps);
                    }
                    unsigned mB = __ballot_sync(FULL, cB);
                    while (mB) {
                        const int src = __ffs(mB) - 1;
                        mB &= mB - 1;
                        const float cs  = __shfl_sync(FULL, sB, src);
                        const int   cps = __shfl_sync(FULL, posB, src);
                        const int   coj = idx_s[cps];
                        INSERT_CAND(cs, coj, cps);
                    }
                    if (stopm) break;
                }
                base += dir ? -64 : 64;
            }
        }

        // ---- 5) lanes 0..3 write one neighbor each (row = original index q)
        if (l < KNN) {
            const int ps = (l == 0) ? p0 : (l == 1) ? p1 : (l == 2) ? p2 : p3;
            const float4 nb = pts_s[ps];
            float* __restrict__ o = out + (((size_t)b * NPTS + q) * KNN + l) * 3;
            o[0] = nb.x; o[1] = nb.y; o[2] = nb.z;
        }
    }
}

extern "C" void kernel_launch(void* const* d_in, const int* in_sizes, int n_in,
                              void* d_out, int out_size) {
    (void)n_in; (void)in_sizes; (void)out_size;
    const float* x = (const float*)d_in[0];
    float* out = (float*)d_out;

    cudaFuncSetAttribute(knn_sorted_kernel,
                         cudaFuncAttributeMaxDynamicSharedMemorySize, SMEM_BYTES);

    dim3 grid(GRPX, BATCH, 1);   // 148 blocks = 1 full wave
    dim3 block(THREADS, 1, 1);
    knn_sorted_kernel<<<grid, block, SMEM_BYTES>>>(x, out);
}

// round 14
// speedup vs baseline: 1.4590x; 1.4590x over previous
#include <cuda_runtime.h>
#include <math_constants.h>
#include <limits.h>

#define NPTS   8192
#define BATCH  4
#define KNN    4
#define QPB    224
#define THREADS 896                // 28 warps; warp-cooperative, 8 queries/warp
#define GRPX   37                  // 37*4 = 148 blocks = 1 full wave
#define QPW    8

#define NBINS  512
#define XMIN   (-6.0f)
#define BINW   (12.0f / NBINS)
#define INVW   (NBINS / 12.0f)
#define SLACK  1e-3f               // >> all fp32 rounding at these magnitudes
#define GUARD  64                  // sentinels each side; covers prefetch overshoot

#define PTS_BYTES ((NPTS + 2 * GUARD) * 16)
#define IDX_BYTES (NPTS * 4)
#define SMEM_BYTES (PTS_BYTES + 2 * IDX_BYTES + NBINS * 4 * 2)   // 203776 B

#define FULL 0xFFFFFFFFu

__device__ __forceinline__ int bin_of(float px) {
    int bin = (int)__fmul_rn(__fsub_rn(px, XMIN), INVW);
    return min(max(bin, 0), NBINS - 1);
}

__device__ __forceinline__ bool better(float s, int oj, float v, int iv) {
    return (s > v) | ((s == v) & (oj < iv));
}

// Insert into replicated top-4 (no xlim update here; recomputed per event batch).
#define INSERT_CAND(cs, coj, cps)                                              \
    do {                                                                       \
        if (better(cs, coj, v3, o3)) {                                         \
            if (better(cs, coj, v2, o2)) {                                     \
                v3 = v2; o3 = o2; p3 = p2;                                     \
                if (better(cs, coj, v1, o1)) {                                 \
                    v2 = v1; o2 = o1; p2 = p1;                                 \
                    if (better(cs, coj, v0, o0)) {                             \
                        v1 = v0; o1 = o0; p1 = p0;                             \
                        v0 = cs; o0 = coj; p0 = cps;                           \
                    } else { v1 = cs; o1 = coj; p1 = cps; }                    \
                } else { v2 = cs; o2 = coj; p2 = cps; }                        \
            } else { v3 = cs; o3 = coj; p3 = cps; }                            \
        }                                                                      \
    } while (0)

__global__ __launch_bounds__(THREADS, 1)
void knn_sorted_kernel(const float* __restrict__ x, float* __restrict__ out) {
    extern __shared__ char smem_raw[];
    float4* __restrict__ pts_s   = (float4*)smem_raw + GUARD;   // logical [-GUARD, NPTS+GUARD)
    int*    __restrict__ idx_s   = (int*)(smem_raw + PTS_BYTES);
    int*    __restrict__ rank_of = (int*)(smem_raw + PTS_BYTES + IDX_BYTES);
    int*    __restrict__ cnt     = (int*)(smem_raw + PTS_BYTES + 2 * IDX_BYTES);
    int*    __restrict__ tmp     = cnt + NBINS;

    const int b = blockIdx.y;
    const float* __restrict__ xb = x + (size_t)b * NPTS * 3;
    const int tid = threadIdx.x;

    // ---- 0) sentinels: beyond==true, s==-inf/NaN -> never a candidate
    if (tid < 2 * GUARD) {
        const int pos = (tid < GUARD) ? (tid - GUARD) : (NPTS + tid - GUARD);
        const float gx = (tid < GUARD) ? -1e30f : 1e30f;
        pts_s[pos] = make_float4(gx, 0.0f, 0.0f, -CUDART_INF_F);
    }

    // ---- 1) histogram over x-bins
    for (int i = tid; i < NBINS; i += THREADS) cnt[i] = 0;
    __syncthreads();
    for (int j = tid; j < NPTS; j += THREADS)
        atomicAdd(&cnt[bin_of(xb[3 * j])], 1);
    __syncthreads();

    // ---- 2) exclusive prefix (Kogge-Stone)
    if (tid < NBINS) tmp[tid] = cnt[tid];
    __syncthreads();
    for (int d = 1; d < NBINS; d <<= 1) {
        int v = 0;
        if (tid < NBINS && tid >= d) v = tmp[tid - d];
        __syncthreads();
        if (tid < NBINS) tmp[tid] += v;
        __syncthreads();
    }
    if (tid < NBINS) cnt[tid] = tmp[tid] - cnt[tid];
    __syncthreads();

    // ---- 3) scatter into bin-sorted order; record each original index's rank
    for (int j = tid; j < NPTS; j += THREADS) {
        float px = xb[3 * j + 0];
        float py = xb[3 * j + 1];
        float pz = xb[3 * j + 2];
        int pos = atomicAdd(&cnt[bin_of(px)], 1);
        pts_s[pos] = make_float4(px, py, pz, -0.5f * (px * px + py * py + pz * pz));
        idx_s[pos] = j;
        rank_of[j] = pos;
    }
    __syncthreads();

    // ---- 4) warp-cooperative queries
    const int w = tid >> 5, l = tid & 31;

    for (int qq = 0; qq < QPW; ++qq) {
        const int q = blockIdx.x * QPB + w * QPW + qq;   // warp-uniform
        if (q >= NPTS) break;

        const int r = rank_of[q];
        const float4 qp = pts_s[r];
        const float qx = qp.x, qy = qp.y, qz = qp.z;
        const float qh2 = -2.0f * qp.w;                  // ||q||^2

        float v0, v1, v2, v3;
        int   o0, o1, o2, o3;
        int   p0, p1, p2, p3;
        float d4sq, xlim;

        // ---- 4a) seed: evaluate 32-rank window once, extract exact top-4 by
        //          4 rounds of lexicographic warp argmax reduction (branch-free).
        const int lo = max(0, r - 16);
        const int hi = min(NPTS - 1, r + 15);
        {
            const int pos = lo + l;
            float s  = -CUDART_INF_F;
            int   oj = INT_MAX;
            if (pos <= hi) {
                const float4 p = pts_s[pos];
                s = __fmaf_rn(qx, p.x, p.w);
                s = __fmaf_rn(qy, p.y, s);
                s = __fmaf_rn(qz, p.z, s);
                oj = idx_s[pos];
            }

            float rs[KNN]; int ro[KNN]; int rp[KNN];
            #pragma unroll
            for (int k = 0; k < KNN; ++k) {
                float bs = s; int boj = oj; int bps = pos;
                #pragma unroll
                for (int d = 16; d; d >>= 1) {
                    const float os  = __shfl_xor_sync(FULL, bs, d);
                    const int   ooj = __shfl_xor_sync(FULL, boj, d);
                    const int   ops = __shfl_xor_sync(FULL, bps, d);
                    if (better(os, ooj, bs, boj)) { bs = os; boj = ooj; bps = ops; }
                }
                rs[k] = bs; ro[k] = boj; rp[k] = bps;
                if (oj == boj) s = -CUDART_INF_F;        // oj unique -> mask winner
            }
            v0 = rs[0]; o0 = ro[0]; p0 = rp[0];
            v1 = rs[1]; o1 = ro[1]; p1 = rp[1];
            v2 = rs[2]; o2 = ro[2]; p2 = rp[2];
            v3 = rs[3]; o3 = ro[3]; p3 = rp[3];
            d4sq = qh2 - 2.0f * v3 + SLACK;              // >=16 valid -> v3 finite
            xlim = __fadd_ru(BINW, __fsqrt_ru(d4sq));
        }

        // ---- 4b) chunked walk, 32/chunk, LDS software-pipelined (prefetch next)
        #pragma unroll
        for (int dir = 0; dir < 2; ++dir) {
            const int step = dir ? -32 : 32;
            int pos = dir ? (lo - 1 - l) : (hi + 1 + l);
            float4 p = pts_s[pos];                       // guards make all loads safe

            for (;;) {
                const float4 pn = pts_s[pos + step];     // prefetch next chunk early
                const float dx = dir ? (qx - p.x) : (p.x - qx);
                const bool beyond = dx > xlim;           // sound prune (BINW folded in)
                float s = __fmaf_rn(qx, p.x, p.w);
                s = __fmaf_rn(qy, p.y, s);
                s = __fmaf_rn(qz, p.z, s);
                const bool candp = (s >= v3);            // guards: -inf/NaN -> false

                const unsigned bm = __ballot_sync(FULL, beyond | candp);
                if (bm) {                                // rare after 32-seed
                    const unsigned stopm = __ballot_sync(FULL, beyond);
                    unsigned cand = bm & ~stopm;
                    while (cand) {
                        const int src = __ffs(cand) - 1;
                        cand &= cand - 1;
                        const float cs  = __shfl_sync(FULL, s, src);
                        const int   cps = __shfl_sync(FULL, pos, src);
                        const int   coj = idx_s[cps];
                        INSERT_CAND(cs, coj, cps);
                    }
                    d4sq = qh2 - 2.0f * v3 + SLACK;      // once per event batch
                    xlim = __fadd_ru(BINW, __fsqrt_ru(d4sq));
                    if (stopm) break;
                }
                p = pn;
                pos += step;
            }
        }

        // ---- 5) lanes 0..3 write one neighbor each (row = original index q)
        if (l < KNN) {
            const int ps = (l == 0) ? p0 : (l == 1) ? p1 : (l == 2) ? p2 : p3;
            const float4 nb = pts_s[ps];
            float* __restrict__ o = out + (((size_t)b * NPTS + q) * KNN + l) * 3;
            o[0] = nb.x; o[1] = nb.y; o[2] = nb.z;
        }
    }
}

extern "C" void kernel_launch(void* const* d_in, const int* in_sizes, int n_in,
                              void* d_out, int out_size) {
    (void)n_in; (void)in_sizes; (void)out_size;
    const float* x = (const float*)d_in[0];
    float* out = (float*)d_out;

    cudaFuncSetAttribute(knn_sorted_kernel,
                         cudaFuncAttributeMaxDynamicSharedMemorySize, SMEM_BYTES);

    dim3 grid(GRPX, BATCH, 1);   // 148 blocks = 1 full wave
    dim3 block(THREADS, 1, 1);
    knn_sorted_kernel<<<grid, block, SMEM_BYTES>>>(x, out);
}